// round 15
// baseline (speedup 1.0000x reference)
#include <cuda_runtime.h>
#include <cuda_bf16.h>
#include <cstdint>

#define N_NODES 50000
#define N_EDGES 800000
#define D 128
#define N_LAYERS 3
#define N_GRAPHS 256

#define SCAN_BLK 256
#define SCAN_NBLK ((N_NODES + SCAN_BLK - 1) / SCAN_BLK)   // 196
#define MAXDEG_LOCAL 128

// ---------------- scratch (static device globals) ---------------------------
__device__ float g_agg[N_NODES * D];
__device__ float g_h0[N_NODES * D];
__device__ float g_h1[N_NODES * D];
__device__ __nv_bfloat16 g_Wthi[N_LAYERS * D * D];    // W^T hi (n-major)
__device__ __nv_bfloat16 g_Wtlo[N_LAYERS * D * D];    // W^T lo
__device__ float g_norm_out[N_NODES];
__device__ float g_norm_in[N_NODES];
__device__ int   g_deg_out[N_NODES];
__device__ int   g_deg_in[N_NODES];
__device__ int   g_rowptr[N_NODES + 1];
__device__ int   g_cursor[N_NODES];
__device__ int   g_csr_src[N_EDGES];
__device__ int   g_blocksum[SCAN_NBLK];

// ---------------- W preconversion: [l][k][n] fp32 -> [l][n][k] bf16 hi/lo ---
__global__ void convW_kernel(const float* __restrict__ W) {
    int idx = blockIdx.x * blockDim.x + threadIdx.x;
    if (idx >= N_LAYERS * D * D) return;
    int l = idx >> 14;
    int r = idx & 16383;
    int k = r >> 7, n = r & 127;      // coalesced read over n
    float w = W[idx];
    __nv_bfloat16 hi = __float2bfloat16(w);
    __nv_bfloat16 lo = __float2bfloat16(w - __bfloat162float(hi));
    int o = (l << 14) + (n << 7) + k;
    g_Wthi[o] = hi;
    g_Wtlo[o] = lo;
}

// ---------------- graph preprocessing --------------------------------------
__global__ void count_deg_kernel(const int* __restrict__ src,
                                 const int* __restrict__ dst) {
    int t = blockIdx.x * blockDim.x + threadIdx.x;
    int base = t * 4;
    if (base + 3 < N_EDGES) {
        int4 s = *(const int4*)(src + base);
        int4 d = *(const int4*)(dst + base);
        atomicAdd(&g_deg_out[s.x], 1); atomicAdd(&g_deg_out[s.y], 1);
        atomicAdd(&g_deg_out[s.z], 1); atomicAdd(&g_deg_out[s.w], 1);
        atomicAdd(&g_deg_in[d.x], 1);  atomicAdd(&g_deg_in[d.y], 1);
        atomicAdd(&g_deg_in[d.z], 1);  atomicAdd(&g_deg_in[d.w], 1);
    } else {
        for (int i = base; i < N_EDGES; i++) {
            atomicAdd(&g_deg_out[src[i]], 1);
            atomicAdd(&g_deg_in[dst[i]], 1);
        }
    }
}

// per-block sums of deg_in + fused norm computation
__global__ void scanA_kernel() {
    __shared__ int warp_sum[SCAN_BLK / 32];
    int i = blockIdx.x * SCAN_BLK + threadIdx.x;
    int v = 0;
    if (i < N_NODES) {
        int din = g_deg_in[i];
        v = din;
        g_norm_out[i] = rsqrtf((float)max(g_deg_out[i], 1));
        g_norm_in[i]  = rsqrtf((float)max(din, 1));
    }
    int s = v;
#pragma unroll
    for (int off = 16; off > 0; off >>= 1)
        s += __shfl_down_sync(0xffffffffu, s, off);
    if ((threadIdx.x & 31) == 0) warp_sum[threadIdx.x >> 5] = s;
    __syncthreads();
    if (threadIdx.x < SCAN_BLK / 32) {
        int ws = warp_sum[threadIdx.x];
#pragma unroll
        for (int off = SCAN_BLK / 64; off > 0; off >>= 1)
            ws += __shfl_down_sync(0xffffffffu, ws, off);
        if (threadIdx.x == 0) g_blocksum[blockIdx.x] = ws;
    }
}

// fused: per-block offset (warp-reduce over blocksums) + local scan -> rowptr
__global__ void scanC_kernel() {
    __shared__ int sm[SCAN_BLK];
    __shared__ int s_off;
    const int b = blockIdx.x, t = threadIdx.x;
    if (t < 32) {
        int s = 0;
        for (int i = t; i < b; i += 32) s += g_blocksum[i];
#pragma unroll
        for (int o = 16; o > 0; o >>= 1) s += __shfl_down_sync(0xffffffffu, s, o);
        if (t == 0) s_off = s;
    }
    int i = b * SCAN_BLK + t;
    int v = (i < N_NODES) ? g_deg_in[i] : 0;
    sm[t] = v;
    __syncthreads();
#pragma unroll
    for (int off = 1; off < SCAN_BLK; off <<= 1) {
        int add = (t >= off) ? sm[t - off] : 0;
        __syncthreads();
        sm[t] += add;
        __syncthreads();
    }
    if (i < N_NODES) {
        int rp = s_off + sm[t] - v;   // exclusive
        g_rowptr[i] = rp;
        g_cursor[i] = rp;
        if (i == N_NODES - 1) g_rowptr[N_NODES] = rp + v;
    }
}

__global__ void bucket_kernel(const int* __restrict__ src,
                              const int* __restrict__ dst) {
    int i = blockIdx.x * blockDim.x + threadIdx.x;
    if (i < N_EDGES) {
        int d = dst[i];
        int pos = atomicAdd(&g_cursor[d], 1);
        g_csr_src[pos] = src[i];
    }
}

__global__ void sort_csr_kernel() {
    int n = blockIdx.x * blockDim.x + threadIdx.x;
    if (n >= N_NODES) return;
    int beg = g_rowptr[n], end = g_rowptr[n + 1];
    int d = end - beg;
    if (d <= 1) return;
    if (d <= MAXDEG_LOCAL) {
        int buf[MAXDEG_LOCAL];
        for (int i = 0; i < d; i++) buf[i] = g_csr_src[beg + i];
        for (int i = 1; i < d; i++) {
            int v = buf[i];
            int j = i - 1;
            while (j >= 0 && buf[j] > v) { buf[j + 1] = buf[j]; j--; }
            buf[j + 1] = v;
        }
        for (int i = 0; i < d; i++) g_csr_src[beg + i] = buf[i];
    } else {
        for (int i = beg + 1; i < end; i++) {
            int v = g_csr_src[i];
            int j = i - 1;
            while (j >= beg && g_csr_src[j] > v) {
                g_csr_src[j + 1] = g_csr_src[j];
                j--;
            }
            g_csr_src[j + 1] = v;
        }
    }
}

// ---------------- SpMM (fp32 gather, 8-edge unroll for MLP) -----------------
__global__ void spmm_kernel(const float* __restrict__ feats, int in_sel) {
    const float* __restrict__ in =
        (in_sel == 0) ? feats : ((in_sel == 1) ? g_h0 : g_h1);
    int gwarp = (blockIdx.x * blockDim.x + threadIdx.x) >> 5;
    int lane = threadIdx.x & 31;
    if (gwarp >= N_NODES) return;
    int beg = g_rowptr[gwarp], end = g_rowptr[gwarp + 1];
    float4 acc = make_float4(0.f, 0.f, 0.f, 0.f);
    int e = beg;
    for (; e + 7 < end; e += 8) {
        int s0 = g_csr_src[e],     s1 = g_csr_src[e + 1];
        int s2 = g_csr_src[e + 2], s3 = g_csr_src[e + 3];
        int s4 = g_csr_src[e + 4], s5 = g_csr_src[e + 5];
        int s6 = g_csr_src[e + 6], s7 = g_csr_src[e + 7];
        float w0 = g_norm_out[s0], w1 = g_norm_out[s1];
        float w2 = g_norm_out[s2], w3 = g_norm_out[s3];
        float w4 = g_norm_out[s4], w5 = g_norm_out[s5];
        float w6 = g_norm_out[s6], w7 = g_norm_out[s7];
        float4 v0 = ((const float4*)(in + s0 * D))[lane];
        float4 v1 = ((const float4*)(in + s1 * D))[lane];
        float4 v2 = ((const float4*)(in + s2 * D))[lane];
        float4 v3 = ((const float4*)(in + s3 * D))[lane];
        float4 v4 = ((const float4*)(in + s4 * D))[lane];
        float4 v5 = ((const float4*)(in + s5 * D))[lane];
        float4 v6 = ((const float4*)(in + s6 * D))[lane];
        float4 v7 = ((const float4*)(in + s7 * D))[lane];
        acc.x += w0 * v0.x + w1 * v1.x + w2 * v2.x + w3 * v3.x
               + w4 * v4.x + w5 * v5.x + w6 * v6.x + w7 * v7.x;
        acc.y += w0 * v0.y + w1 * v1.y + w2 * v2.y + w3 * v3.y
               + w4 * v4.y + w5 * v5.y + w6 * v6.y + w7 * v7.y;
        acc.z += w0 * v0.z + w1 * v1.z + w2 * v2.z + w3 * v3.z
               + w4 * v4.z + w5 * v5.z + w6 * v6.z + w7 * v7.z;
        acc.w += w0 * v0.w + w1 * v1.w + w2 * v2.w + w3 * v3.w
               + w4 * v4.w + w5 * v5.w + w6 * v6.w + w7 * v7.w;
    }
    for (; e + 3 < end; e += 4) {
        int s0 = g_csr_src[e],     s1 = g_csr_src[e + 1];
        int s2 = g_csr_src[e + 2], s3 = g_csr_src[e + 3];
        float w0 = g_norm_out[s0], w1 = g_norm_out[s1];
        float w2 = g_norm_out[s2], w3 = g_norm_out[s3];
        float4 v0 = ((const float4*)(in + s0 * D))[lane];
        float4 v1 = ((const float4*)(in + s1 * D))[lane];
        float4 v2 = ((const float4*)(in + s2 * D))[lane];
        float4 v3 = ((const float4*)(in + s3 * D))[lane];
        acc.x += w0 * v0.x + w1 * v1.x + w2 * v2.x + w3 * v3.x;
        acc.y += w0 * v0.y + w1 * v1.y + w2 * v2.y + w3 * v3.y;
        acc.z += w0 * v0.z + w1 * v1.z + w2 * v2.z + w3 * v3.z;
        acc.w += w0 * v0.w + w1 * v1.w + w2 * v2.w + w3 * v3.w;
    }
    for (; e < end; e++) {
        int s0 = g_csr_src[e];
        float w0 = g_norm_out[s0];
        float4 v0 = ((const float4*)(in + s0 * D))[lane];
        acc.x += w0 * v0.x; acc.y += w0 * v0.y;
        acc.z += w0 * v0.z; acc.w += w0 * v0.w;
    }
    float ni = g_norm_in[gwarp];
    acc.x *= ni; acc.y *= ni; acc.z *= ni; acc.w *= ni;
    ((float4*)(g_agg + gwarp * D))[lane] = acc;
}

// ---------------- GEMM via mma.sync bf16, 2 passes + bias + relu ------------
#define AS_STRB 272                         // 136 bf16 per row (pad)
#define SM_A    0
#define SM_BHI  (SM_A + 64 * AS_STRB)       // 17408
#define SM_BLO  (SM_BHI + 128 * AS_STRB)    // 52224
#define SM_TOT  (SM_BLO + 128 * AS_STRB)    // 87040

__device__ __forceinline__ void mma_bf16(float* c, const uint32_t* a,
                                         uint32_t b0, uint32_t b1) {
    asm volatile(
        "mma.sync.aligned.m16n8k16.row.col.f32.bf16.bf16.f32 "
        "{%0,%1,%2,%3}, {%4,%5,%6,%7}, {%8,%9}, {%0,%1,%2,%3};"
        : "+f"(c[0]), "+f"(c[1]), "+f"(c[2]), "+f"(c[3])
        : "r"(a[0]), "r"(a[1]), "r"(a[2]), "r"(a[3]), "r"(b0), "r"(b1));
}

__global__ void __launch_bounds__(128, 2)
gemm_mma_kernel(const __nv_bfloat16* __restrict__ Wthi,
                const __nv_bfloat16* __restrict__ Wtlo,
                const float* __restrict__ bl, int out_sel) {
    extern __shared__ char smem[];
    float* __restrict__ outp = (out_sel == 0) ? g_h0 : g_h1;
    const int tid = threadIdx.x;
    const int wid = tid >> 5, lane = tid & 31;
    const int row0 = blockIdx.x * 64;

    // --- stage A tile (fp32 agg -> single bf16): thread -> row t/2, half t&1
    {
        int r = tid >> 1, ch = tid & 1;
        int grow = row0 + r;
        bool valid = grow < N_NODES;
        const float4* __restrict__ arow =
            (const float4*)(g_agg + (size_t)(valid ? grow : 0) * D);
#pragma unroll
        for (int j0 = 0; j0 < 64; j0 += 8) {
            int c = ch * 64 + j0;
            float4 f0 = valid ? arow[c / 4]     : make_float4(0.f, 0.f, 0.f, 0.f);
            float4 f1 = valid ? arow[c / 4 + 1] : make_float4(0.f, 0.f, 0.f, 0.f);
            __nv_bfloat16 hi[8];
            hi[0] = __float2bfloat16(f0.x); hi[1] = __float2bfloat16(f0.y);
            hi[2] = __float2bfloat16(f0.z); hi[3] = __float2bfloat16(f0.w);
            hi[4] = __float2bfloat16(f1.x); hi[5] = __float2bfloat16(f1.y);
            hi[6] = __float2bfloat16(f1.z); hi[7] = __float2bfloat16(f1.w);
            *(uint4*)(smem + SM_A + r * AS_STRB + c * 2) = *(uint4*)hi;
        }
    }

    // --- stage B from preconverted W^T hi/lo: flat coalesced copy -----------
    {
        const uint4* __restrict__ wh = (const uint4*)Wthi;
        const uint4* __restrict__ wl = (const uint4*)Wtlo;
#pragma unroll
        for (int idx = tid; idx < 128 * 16; idx += 128) {
            int n = idx >> 4, kq = idx & 15;
            *(uint4*)(smem + SM_BHI + n * AS_STRB + kq * 16) = wh[idx];
            *(uint4*)(smem + SM_BLO + n * AS_STRB + kq * 16) = wl[idx];
        }
    }
    __syncthreads();

    // --- main loop ----------------------------------------------------------
    const int wm = wid & 1;        // row half -> +32 rows
    const int wn = wid >> 1;       // col half -> +64 cols
    const int r4 = lane >> 2;      // 0..7
    const int q  = lane & 3;       // 0..3

    float acc[2][8][4];
#pragma unroll
    for (int mt = 0; mt < 2; mt++)
#pragma unroll
        for (int nt = 0; nt < 8; nt++)
#pragma unroll
            for (int j = 0; j < 4; j++) acc[mt][nt][j] = 0.f;

    const char* As    = smem + SM_A;
    const char* Bs_hi = smem + SM_BHI;
    const char* Bs_lo = smem + SM_BLO;

#pragma unroll 2
    for (int kc = 0; kc < 8; kc++) {
        int k0 = kc * 16;
        uint32_t ah[2][4];
#pragma unroll
        for (int mt = 0; mt < 2; mt++) {
            int rm = wm * 32 + mt * 16 + r4;
            int ka = k0 + 2 * q;
            ah[mt][0] = *(const uint32_t*)(As + rm * AS_STRB + ka * 2);
            ah[mt][1] = *(const uint32_t*)(As + (rm + 8) * AS_STRB + ka * 2);
            ah[mt][2] = *(const uint32_t*)(As + rm * AS_STRB + (ka + 8) * 2);
            ah[mt][3] = *(const uint32_t*)(As + (rm + 8) * AS_STRB + (ka + 8) * 2);
        }
#pragma unroll
        for (int nt = 0; nt < 8; nt++) {
            int nn = wn * 64 + nt * 8 + r4;
            int kb = k0 + 2 * q;
            uint32_t bh0 = *(const uint32_t*)(Bs_hi + nn * AS_STRB + kb * 2);
            uint32_t bh1 = *(const uint32_t*)(Bs_hi + nn * AS_STRB + (kb + 8) * 2);
            uint32_t bl0 = *(const uint32_t*)(Bs_lo + nn * AS_STRB + kb * 2);
            uint32_t bl1 = *(const uint32_t*)(Bs_lo + nn * AS_STRB + (kb + 8) * 2);
#pragma unroll
            for (int mt = 0; mt < 2; mt++) {
                mma_bf16(acc[mt][nt], ah[mt], bh0, bh1);
                mma_bf16(acc[mt][nt], ah[mt], bl0, bl1);
            }
        }
    }

    // --- epilogue: bias + relu, float2 stores -------------------------------
#pragma unroll
    for (int mt = 0; mt < 2; mt++) {
#pragma unroll
        for (int nt = 0; nt < 8; nt++) {
            int row = row0 + wm * 32 + mt * 16 + r4;
            int col = wn * 64 + nt * 8 + 2 * q;
            float2 bb = *(const float2*)(bl + col);
            if (row < N_NODES) {
                float2 v;
                v.x = fmaxf(acc[mt][nt][0] + bb.x, 0.f);
                v.y = fmaxf(acc[mt][nt][1] + bb.y, 0.f);
                *(float2*)(outp + (size_t)row * D + col) = v;
            }
            if (row + 8 < N_NODES) {
                float2 v;
                v.x = fmaxf(acc[mt][nt][2] + bb.x, 0.f);
                v.y = fmaxf(acc[mt][nt][3] + bb.y, 0.f);
                *(float2*)(outp + (size_t)(row + 8) * D + col) = v;
            }
        }
    }
}

// ---------------- pooling ---------------------------------------------------
__device__ __forceinline__ int lower_bound_dev(const int* __restrict__ a,
                                               int n, int key) {
    int lo = 0, hi = n;
    while (lo < hi) {
        int mid = (lo + hi) >> 1;
        if (a[mid] < key) lo = mid + 1; else hi = mid;
    }
    return lo;
}

__global__ void pool_kernel(const int* __restrict__ gid,
                            float* __restrict__ out) {
    __shared__ int s_beg, s_end;
    int g = blockIdx.x;
    if (threadIdx.x == 0) {
        s_beg = lower_bound_dev(gid, N_NODES, g);
        s_end = lower_bound_dev(gid, N_NODES, g + 1);
    }
    __syncthreads();
    int beg = s_beg, end = s_end;
    const float* __restrict__ h = g_h0;
    float acc = 0.f;
    for (int n = beg; n < end; n++) acc += h[n * D + threadIdx.x];
    float cnt = (float)max(end - beg, 1);
    out[g * D + threadIdx.x] = acc / cnt;
}

// ---------------- launch ----------------------------------------------------
extern "C" void kernel_launch(void* const* d_in, const int* in_sizes, int n_in,
                              void* d_out, int out_size) {
    const float* feats = (const float*)d_in[0];
    const float* W     = (const float*)d_in[1];
    const float* b     = (const float*)d_in[2];
    const int*   src   = (const int*)d_in[3];
    const int*   dst   = (const int*)d_in[4];
    const int*   gid   = (const int*)d_in[5];
    float* out = (float*)d_out;

    cudaFuncSetAttribute(gemm_mma_kernel,
                         cudaFuncAttributeMaxDynamicSharedMemorySize, SM_TOT);

    __nv_bfloat16 *wthi_p, *wtlo_p;
    cudaGetSymbolAddress((void**)&wthi_p, g_Wthi);
    cudaGetSymbolAddress((void**)&wtlo_p, g_Wtlo);
    int *dego_p, *degi_p;
    cudaGetSymbolAddress((void**)&dego_p, g_deg_out);
    cudaGetSymbolAddress((void**)&degi_p, g_deg_in);

    const int NODE_BLKS = (N_NODES + 255) / 256;           // 196
    const int EDGE_BLKS = (N_EDGES + 255) / 256;           // 3125
    const int CNT_BLKS  = (N_EDGES / 4 + 255) / 256;       // 782
    const int CW_BLKS   = (N_LAYERS * D * D + 255) / 256;  // 192

    cudaMemsetAsync(dego_p, 0, N_NODES * sizeof(int));
    cudaMemsetAsync(degi_p, 0, N_NODES * sizeof(int));
    convW_kernel<<<CW_BLKS, 256>>>(W);
    count_deg_kernel<<<CNT_BLKS, 256>>>(src, dst);
    scanA_kernel<<<SCAN_NBLK, SCAN_BLK>>>();
    scanC_kernel<<<SCAN_NBLK, SCAN_BLK>>>();
    bucket_kernel<<<EDGE_BLKS, 256>>>(src, dst);
    sort_csr_kernel<<<NODE_BLKS, 256>>>();

    const int SPMM_BLKS = N_NODES / 8;                     // 6250
    const int GEMM_BLKS = (N_NODES + 63) / 64;             // 782

    spmm_kernel<<<SPMM_BLKS, 256>>>(feats, 0);
    gemm_mma_kernel<<<GEMM_BLKS, 128, SM_TOT>>>(wthi_p, wtlo_p, b + 0 * D, 0);
    spmm_kernel<<<SPMM_BLKS, 256>>>(feats, 1);
    gemm_mma_kernel<<<GEMM_BLKS, 128, SM_TOT>>>(wthi_p + D * D,
                                                wtlo_p + D * D, b + 1 * D, 1);
    spmm_kernel<<<SPMM_BLKS, 256>>>(feats, 2);
    gemm_mma_kernel<<<GEMM_BLKS, 128, SM_TOT>>>(wthi_p + 2 * D * D,
                                                wtlo_p + 2 * D * D, b + 2 * D, 0);

    pool_kernel<<<N_GRAPHS, 128>>>(gid, out);
}

// round 16
// speedup vs baseline: 1.0409x; 1.0409x over previous
#include <cuda_runtime.h>
#include <cuda_bf16.h>
#include <cstdint>

#define N_NODES 50000
#define N_EDGES 800000
#define D 128
#define N_LAYERS 3
#define N_GRAPHS 256

#define SCAN_BLK 256
#define SCAN_NBLK ((N_NODES + SCAN_BLK - 1) / SCAN_BLK)   // 196
#define MAXDEG_LOCAL 128

// ---------------- scratch (static device globals) ---------------------------
__device__ float g_agg[N_NODES * D];
__device__ float g_h0[N_NODES * D];
__device__ float g_h1[N_NODES * D];
__device__ __nv_bfloat16 g_Wthi[N_LAYERS * D * D];    // W^T hi (n-major)
__device__ __nv_bfloat16 g_Wtlo[N_LAYERS * D * D];    // W^T lo
__device__ float g_norm_out[N_NODES];
__device__ float g_norm_in[N_NODES];
__device__ int   g_deg_out[N_NODES];
__device__ int   g_deg_in[N_NODES];
__device__ int   g_rowptr[N_NODES + 1];
__device__ int   g_cursor[N_NODES];
__device__ int   g_csr_src[N_EDGES];
__device__ int   g_blocksum[SCAN_NBLK];

// ---------------- W preconversion: [l][k][n] fp32 -> [l][n][k] bf16 hi/lo ---
__global__ void convW_kernel(const float* __restrict__ W) {
    int idx = blockIdx.x * blockDim.x + threadIdx.x;
    if (idx >= N_LAYERS * D * D) return;
    int l = idx >> 14;
    int r = idx & 16383;
    int k = r >> 7, n = r & 127;      // coalesced read over n
    float w = W[idx];
    __nv_bfloat16 hi = __float2bfloat16(w);
    __nv_bfloat16 lo = __float2bfloat16(w - __bfloat162float(hi));
    int o = (l << 14) + (n << 7) + k;
    g_Wthi[o] = hi;
    g_Wtlo[o] = lo;
}

// ---------------- graph preprocessing --------------------------------------
__global__ void count_deg_kernel(const int* __restrict__ src,
                                 const int* __restrict__ dst) {
    int t = blockIdx.x * blockDim.x + threadIdx.x;
    int base = t * 4;
    if (base + 3 < N_EDGES) {
        int4 s = *(const int4*)(src + base);
        int4 d = *(const int4*)(dst + base);
        atomicAdd(&g_deg_out[s.x], 1); atomicAdd(&g_deg_out[s.y], 1);
        atomicAdd(&g_deg_out[s.z], 1); atomicAdd(&g_deg_out[s.w], 1);
        atomicAdd(&g_deg_in[d.x], 1);  atomicAdd(&g_deg_in[d.y], 1);
        atomicAdd(&g_deg_in[d.z], 1);  atomicAdd(&g_deg_in[d.w], 1);
    } else {
        for (int i = base; i < N_EDGES; i++) {
            atomicAdd(&g_deg_out[src[i]], 1);
            atomicAdd(&g_deg_in[dst[i]], 1);
        }
    }
}

// per-block sums of deg_in + fused norm computation
__global__ void scanA_kernel() {
    __shared__ int warp_sum[SCAN_BLK / 32];
    int i = blockIdx.x * SCAN_BLK + threadIdx.x;
    int v = 0;
    if (i < N_NODES) {
        int din = g_deg_in[i];
        v = din;
        g_norm_out[i] = rsqrtf((float)max(g_deg_out[i], 1));
        g_norm_in[i]  = rsqrtf((float)max(din, 1));
    }
    int s = v;
#pragma unroll
    for (int off = 16; off > 0; off >>= 1)
        s += __shfl_down_sync(0xffffffffu, s, off);
    if ((threadIdx.x & 31) == 0) warp_sum[threadIdx.x >> 5] = s;
    __syncthreads();
    if (threadIdx.x < SCAN_BLK / 32) {
        int ws = warp_sum[threadIdx.x];
#pragma unroll
        for (int off = SCAN_BLK / 64; off > 0; off >>= 1)
            ws += __shfl_down_sync(0xffffffffu, ws, off);
        if (threadIdx.x == 0) g_blocksum[blockIdx.x] = ws;
    }
}

// fused: per-block offset (warp-reduce over blocksums) + local scan -> rowptr
__global__ void scanC_kernel() {
    __shared__ int sm[SCAN_BLK];
    __shared__ int s_off;
    const int b = blockIdx.x, t = threadIdx.x;
    if (t < 32) {
        int s = 0;
        for (int i = t; i < b; i += 32) s += g_blocksum[i];
#pragma unroll
        for (int o = 16; o > 0; o >>= 1) s += __shfl_down_sync(0xffffffffu, s, o);
        if (t == 0) s_off = s;
    }
    int i = b * SCAN_BLK + t;
    int v = (i < N_NODES) ? g_deg_in[i] : 0;
    sm[t] = v;
    __syncthreads();
#pragma unroll
    for (int off = 1; off < SCAN_BLK; off <<= 1) {
        int add = (t >= off) ? sm[t - off] : 0;
        __syncthreads();
        sm[t] += add;
        __syncthreads();
    }
    if (i < N_NODES) {
        int rp = s_off + sm[t] - v;   // exclusive
        g_rowptr[i] = rp;
        g_cursor[i] = rp;
        if (i == N_NODES - 1) g_rowptr[N_NODES] = rp + v;
    }
}

__global__ void bucket_kernel(const int* __restrict__ src,
                              const int* __restrict__ dst) {
    int i = blockIdx.x * blockDim.x + threadIdx.x;
    if (i < N_EDGES) {
        int d = dst[i];
        int pos = atomicAdd(&g_cursor[d], 1);
        g_csr_src[pos] = src[i];
    }
}

__global__ void sort_csr_kernel() {
    int n = blockIdx.x * blockDim.x + threadIdx.x;
    if (n >= N_NODES) return;
    int beg = g_rowptr[n], end = g_rowptr[n + 1];
    int d = end - beg;
    if (d <= 1) return;
    if (d <= MAXDEG_LOCAL) {
        int buf[MAXDEG_LOCAL];
        for (int i = 0; i < d; i++) buf[i] = g_csr_src[beg + i];
        for (int i = 1; i < d; i++) {
            int v = buf[i];
            int j = i - 1;
            while (j >= 0 && buf[j] > v) { buf[j + 1] = buf[j]; j--; }
            buf[j + 1] = v;
        }
        for (int i = 0; i < d; i++) g_csr_src[beg + i] = buf[i];
    } else {
        for (int i = beg + 1; i < end; i++) {
            int v = g_csr_src[i];
            int j = i - 1;
            while (j >= beg && g_csr_src[j] > v) {
                g_csr_src[j + 1] = g_csr_src[j];
                j--;
            }
            g_csr_src[j + 1] = v;
        }
    }
}

// ---------------- SpMM (fp32 gather, proven 4-edge unroll) ------------------
__global__ void spmm_kernel(const float* __restrict__ feats, int in_sel) {
    const float* __restrict__ in =
        (in_sel == 0) ? feats : ((in_sel == 1) ? g_h0 : g_h1);
    int gwarp = (blockIdx.x * blockDim.x + threadIdx.x) >> 5;
    int lane = threadIdx.x & 31;
    if (gwarp >= N_NODES) return;
    int beg = g_rowptr[gwarp], end = g_rowptr[gwarp + 1];
    float4 acc = make_float4(0.f, 0.f, 0.f, 0.f);
    int e = beg;
    for (; e + 3 < end; e += 4) {
        int s0 = g_csr_src[e],     s1 = g_csr_src[e + 1];
        int s2 = g_csr_src[e + 2], s3 = g_csr_src[e + 3];
        float w0 = g_norm_out[s0], w1 = g_norm_out[s1];
        float w2 = g_norm_out[s2], w3 = g_norm_out[s3];
        float4 v0 = ((const float4*)(in + s0 * D))[lane];
        float4 v1 = ((const float4*)(in + s1 * D))[lane];
        float4 v2 = ((const float4*)(in + s2 * D))[lane];
        float4 v3 = ((const float4*)(in + s3 * D))[lane];
        acc.x += w0 * v0.x + w1 * v1.x + w2 * v2.x + w3 * v3.x;
        acc.y += w0 * v0.y + w1 * v1.y + w2 * v2.y + w3 * v3.y;
        acc.z += w0 * v0.z + w1 * v1.z + w2 * v2.z + w3 * v3.z;
        acc.w += w0 * v0.w + w1 * v1.w + w2 * v2.w + w3 * v3.w;
    }
    for (; e < end; e++) {
        int s0 = g_csr_src[e];
        float w0 = g_norm_out[s0];
        float4 v0 = ((const float4*)(in + s0 * D))[lane];
        acc.x += w0 * v0.x; acc.y += w0 * v0.y;
        acc.z += w0 * v0.z; acc.w += w0 * v0.w;
    }
    float ni = g_norm_in[gwarp];
    acc.x *= ni; acc.y *= ni; acc.z *= ni; acc.w *= ni;
    ((float4*)(g_agg + gwarp * D))[lane] = acc;
}

// ---------------- GEMM via mma.sync bf16, 2 passes + bias + relu ------------
// block = 256 thr (8 warps), tile 128 rows x 128 cols, K=128.
// Warp (wm 0..3, wn 0..1): 32 rows x 64 cols = 2 m-tiles(16) x 8 n-tiles(8).
// 2 passes per k-chunk: Ahi*Bhi + Ahi*Blo (W captured hi/lo; A single bf16 --
// A-quantization errors are per-node-independent and pool-average away).
#define AS_STRB 272                          // 136 bf16 per row (pad)
#define SM_A    0
#define SM_BHI  (SM_A + 128 * AS_STRB)       // 34816
#define SM_BLO  (SM_BHI + 128 * AS_STRB)     // 69632
#define SM_TOT  (SM_BLO + 128 * AS_STRB)     // 104448

__device__ __forceinline__ void mma_bf16(float* c, const uint32_t* a,
                                         uint32_t b0, uint32_t b1) {
    asm volatile(
        "mma.sync.aligned.m16n8k16.row.col.f32.bf16.bf16.f32 "
        "{%0,%1,%2,%3}, {%4,%5,%6,%7}, {%8,%9}, {%0,%1,%2,%3};"
        : "+f"(c[0]), "+f"(c[1]), "+f"(c[2]), "+f"(c[3])
        : "r"(a[0]), "r"(a[1]), "r"(a[2]), "r"(a[3]), "r"(b0), "r"(b1));
}

__global__ void __launch_bounds__(256, 2)
gemm_mma_kernel(const __nv_bfloat16* __restrict__ Wthi,
                const __nv_bfloat16* __restrict__ Wtlo,
                const float* __restrict__ bl, int out_sel) {
    extern __shared__ char smem[];
    float* __restrict__ outp = (out_sel == 0) ? g_h0 : g_h1;
    const int tid = threadIdx.x;
    const int wid = tid >> 5, lane = tid & 31;
    const int row0 = blockIdx.x * 128;

    // --- stage A tile (fp32 agg -> single bf16): thread -> row t/2, half t&1
    {
        int r = tid >> 1, ch = tid & 1;
        int grow = row0 + r;
        bool valid = grow < N_NODES;
        const float4* __restrict__ arow =
            (const float4*)(g_agg + (size_t)(valid ? grow : 0) * D);
#pragma unroll
        for (int j0 = 0; j0 < 64; j0 += 8) {
            int c = ch * 64 + j0;
            float4 f0 = valid ? arow[c / 4]     : make_float4(0.f, 0.f, 0.f, 0.f);
            float4 f1 = valid ? arow[c / 4 + 1] : make_float4(0.f, 0.f, 0.f, 0.f);
            __nv_bfloat16 hi[8];
            hi[0] = __float2bfloat16(f0.x); hi[1] = __float2bfloat16(f0.y);
            hi[2] = __float2bfloat16(f0.z); hi[3] = __float2bfloat16(f0.w);
            hi[4] = __float2bfloat16(f1.x); hi[5] = __float2bfloat16(f1.y);
            hi[6] = __float2bfloat16(f1.z); hi[7] = __float2bfloat16(f1.w);
            *(uint4*)(smem + SM_A + r * AS_STRB + c * 2) = *(uint4*)hi;
        }
    }

    // --- stage B from preconverted W^T hi/lo: flat coalesced copy -----------
    // 128 rows x 16 uint4 per buffer; idx -> (n = idx/16, kq = idx%16)
    {
        const uint4* __restrict__ wh = (const uint4*)Wthi;
        const uint4* __restrict__ wl = (const uint4*)Wtlo;
#pragma unroll
        for (int idx = tid; idx < 128 * 16; idx += 256) {
            int n = idx >> 4, kq = idx & 15;
            *(uint4*)(smem + SM_BHI + n * AS_STRB + kq * 16) = wh[idx];
            *(uint4*)(smem + SM_BLO + n * AS_STRB + kq * 16) = wl[idx];
        }
    }
    __syncthreads();

    // --- main loop ----------------------------------------------------------
    const int wm = wid & 3;        // row quarter -> +32 rows each
    const int wn = wid >> 2;       // col half    -> +64 cols
    const int r4 = lane >> 2;      // 0..7
    const int q  = lane & 3;       // 0..3

    float acc[2][8][4];
#pragma unroll
    for (int mt = 0; mt < 2; mt++)
#pragma unroll
        for (int nt = 0; nt < 8; nt++)
#pragma unroll
            for (int j = 0; j < 4; j++) acc[mt][nt][j] = 0.f;

    const char* As    = smem + SM_A;
    const char* Bs_hi = smem + SM_BHI;
    const char* Bs_lo = smem + SM_BLO;

#pragma unroll 2
    for (int kc = 0; kc < 8; kc++) {
        int k0 = kc * 16;
        uint32_t ah[2][4];
#pragma unroll
        for (int mt = 0; mt < 2; mt++) {
            int rm = wm * 32 + mt * 16 + r4;
            int ka = k0 + 2 * q;
            ah[mt][0] = *(const uint32_t*)(As + rm * AS_STRB + ka * 2);
            ah[mt][1] = *(const uint32_t*)(As + (rm + 8) * AS_STRB + ka * 2);
            ah[mt][2] = *(const uint32_t*)(As + rm * AS_STRB + (ka + 8) * 2);
            ah[mt][3] = *(const uint32_t*)(As + (rm + 8) * AS_STRB + (ka + 8) * 2);
        }
#pragma unroll
        for (int nt = 0; nt < 8; nt++) {
            int nn = wn * 64 + nt * 8 + r4;
            int kb = k0 + 2 * q;
            uint32_t bh0 = *(const uint32_t*)(Bs_hi + nn * AS_STRB + kb * 2);
            uint32_t bh1 = *(const uint32_t*)(Bs_hi + nn * AS_STRB + (kb + 8) * 2);
            uint32_t bl0 = *(const uint32_t*)(Bs_lo + nn * AS_STRB + kb * 2);
            uint32_t bl1 = *(const uint32_t*)(Bs_lo + nn * AS_STRB + (kb + 8) * 2);
#pragma unroll
            for (int mt = 0; mt < 2; mt++) {
                mma_bf16(acc[mt][nt], ah[mt], bh0, bh1);
                mma_bf16(acc[mt][nt], ah[mt], bl0, bl1);
            }
        }
    }

    // --- epilogue: bias + relu, float2 stores -------------------------------
#pragma unroll
    for (int mt = 0; mt < 2; mt++) {
#pragma unroll
        for (int nt = 0; nt < 8; nt++) {
            int row = row0 + wm * 32 + mt * 16 + r4;
            int col = wn * 64 + nt * 8 + 2 * q;
            float2 bb = *(const float2*)(bl + col);
            if (row < N_NODES) {
                float2 v;
                v.x = fmaxf(acc[mt][nt][0] + bb.x, 0.f);
                v.y = fmaxf(acc[mt][nt][1] + bb.y, 0.f);
                *(float2*)(outp + (size_t)row * D + col) = v;
            }
            if (row + 8 < N_NODES) {
                float2 v;
                v.x = fmaxf(acc[mt][nt][2] + bb.x, 0.f);
                v.y = fmaxf(acc[mt][nt][3] + bb.y, 0.f);
                *(float2*)(outp + (size_t)(row + 8) * D + col) = v;
            }
        }
    }
}

// ---------------- pooling ---------------------------------------------------
__device__ __forceinline__ int lower_bound_dev(const int* __restrict__ a,
                                               int n, int key) {
    int lo = 0, hi = n;
    while (lo < hi) {
        int mid = (lo + hi) >> 1;
        if (a[mid] < key) lo = mid + 1; else hi = mid;
    }
    return lo;
}

__global__ void pool_kernel(const int* __restrict__ gid,
                            float* __restrict__ out) {
    __shared__ int s_beg, s_end;
    int g = blockIdx.x;
    if (threadIdx.x == 0) {
        s_beg = lower_bound_dev(gid, N_NODES, g);
        s_end = lower_bound_dev(gid, N_NODES, g + 1);
    }
    __syncthreads();
    int beg = s_beg, end = s_end;
    const float* __restrict__ h = g_h0;
    float acc = 0.f;
    for (int n = beg; n < end; n++) acc += h[n * D + threadIdx.x];
    float cnt = (float)max(end - beg, 1);
    out[g * D + threadIdx.x] = acc / cnt;
}

// ---------------- launch ----------------------------------------------------
extern "C" void kernel_launch(void* const* d_in, const int* in_sizes, int n_in,
                              void* d_out, int out_size) {
    const float* feats = (const float*)d_in[0];
    const float* W     = (const float*)d_in[1];
    const float* b     = (const float*)d_in[2];
    const int*   src   = (const int*)d_in[3];
    const int*   dst   = (const int*)d_in[4];
    const int*   gid   = (const int*)d_in[5];
    float* out = (float*)d_out;

    cudaFuncSetAttribute(gemm_mma_kernel,
                         cudaFuncAttributeMaxDynamicSharedMemorySize, SM_TOT);

    __nv_bfloat16 *wthi_p, *wtlo_p;
    cudaGetSymbolAddress((void**)&wthi_p, g_Wthi);
    cudaGetSymbolAddress((void**)&wtlo_p, g_Wtlo);
    int *dego_p, *degi_p;
    cudaGetSymbolAddress((void**)&dego_p, g_deg_out);
    cudaGetSymbolAddress((void**)&degi_p, g_deg_in);

    const int NODE_BLKS = (N_NODES + 255) / 256;           // 196
    const int EDGE_BLKS = (N_EDGES + 255) / 256;           // 3125
    const int CNT_BLKS  = (N_EDGES / 4 + 255) / 256;       // 782
    const int CW_BLKS   = (N_LAYERS * D * D + 255) / 256;  // 192

    cudaMemsetAsync(dego_p, 0, N_NODES * sizeof(int));
    cudaMemsetAsync(degi_p, 0, N_NODES * sizeof(int));
    convW_kernel<<<CW_BLKS, 256>>>(W);
    count_deg_kernel<<<CNT_BLKS, 256>>>(src, dst);
    scanA_kernel<<<SCAN_NBLK, SCAN_BLK>>>();
    scanC_kernel<<<SCAN_NBLK, SCAN_BLK>>>();
    bucket_kernel<<<EDGE_BLKS, 256>>>(src, dst);
    sort_csr_kernel<<<NODE_BLKS, 256>>>();

    const int SPMM_BLKS = N_NODES / 8;                     // 6250
    const int GEMM_BLKS = (N_NODES + 127) / 128;           // 391

    spmm_kernel<<<SPMM_BLKS, 256>>>(feats, 0);
    gemm_mma_kernel<<<GEMM_BLKS, 256, SM_TOT>>>(wthi_p, wtlo_p, b + 0 * D, 0);
    spmm_kernel<<<SPMM_BLKS, 256>>>(feats, 1);
    gemm_mma_kernel<<<GEMM_BLKS, 256, SM_TOT>>>(wthi_p + D * D,
                                                wtlo_p + D * D, b + 1 * D, 1);
    spmm_kernel<<<SPMM_BLKS, 256>>>(feats, 2);
    gemm_mma_kernel<<<GEMM_BLKS, 256, SM_TOT>>>(wthi_p + 2 * D * D,
                                                wtlo_p + 2 * D * D, b + 2 * D, 0);

    pool_kernel<<<N_GRAPHS, 128>>>(gid, out);
}

// round 17
// speedup vs baseline: 1.1197x; 1.0758x over previous
#include <cuda_runtime.h>
#include <cuda_bf16.h>
#include <cstdint>

#define N_NODES 50000
#define N_EDGES 800000
#define D 128
#define N_LAYERS 3
#define N_GRAPHS 256

#define SCAN_BLK 256
#define SCAN_NBLK ((N_NODES + SCAN_BLK - 1) / SCAN_BLK)   // 196
#define MAXDEG_LOCAL 128

// ---------------- scratch (static device globals) ---------------------------
__device__ float g_agg[N_NODES * D];                  // SpMM out (fp32)
__device__ float g_h0[N_NODES * D];                   // final layer out (fp32)
__device__ __nv_bfloat16 g_fb[N_NODES * D];           // feats*norm_out (bf16)
__device__ __nv_bfloat16 g_hb0[N_NODES * D];          // layer0 out*norm_out
__device__ __nv_bfloat16 g_hb1[N_NODES * D];          // layer1 out*norm_out
__device__ __nv_bfloat16 g_Wthi[N_LAYERS * D * D];    // W^T hi (n-major)
__device__ __nv_bfloat16 g_Wtlo[N_LAYERS * D * D];    // W^T lo
__device__ float g_norm_out[N_NODES];
__device__ float g_norm_in[N_NODES];
__device__ int   g_deg_out[N_NODES];
__device__ int   g_deg_in[N_NODES];
__device__ int   g_rowptr[N_NODES + 1];
__device__ int   g_cursor[N_NODES];
__device__ int   g_csr_src[N_EDGES];
__device__ int   g_blocksum[SCAN_NBLK];
__device__ int   g_blockoff[SCAN_NBLK];

// ---------------- W preconversion: [l][k][n] fp32 -> [l][n][k] bf16 hi/lo ---
__global__ void convW_kernel(const float* __restrict__ W) {
    int idx = blockIdx.x * blockDim.x + threadIdx.x;
    if (idx >= N_LAYERS * D * D) return;
    int l = idx >> 14;
    int r = idx & 16383;
    int k = r >> 7, n = r & 127;      // coalesced read over n
    float w = W[idx];
    __nv_bfloat16 hi = __float2bfloat16(w);
    __nv_bfloat16 lo = __float2bfloat16(w - __bfloat162float(hi));
    int o = (l << 14) + (n << 7) + k;
    g_Wthi[o] = hi;
    g_Wtlo[o] = lo;
}

// ---------------- feats*norm_out -> bf16 ------------------------------------
__global__ void convF_kernel(const float* __restrict__ feats) {
    int i = blockIdx.x * blockDim.x + threadIdx.x;   // per float4
    if (i >= N_NODES * D / 4) return;
    int row = i >> 5;                                // 32 float4 per row
    float w = g_norm_out[row];
    float4 f = ((const float4*)feats)[i];
    __nv_bfloat162 a = __floats2bfloat162_rn(f.x * w, f.y * w);
    __nv_bfloat162 b = __floats2bfloat162_rn(f.z * w, f.w * w);
    uint2 pk;
    pk.x = *(uint32_t*)&a;
    pk.y = *(uint32_t*)&b;
    ((uint2*)g_fb)[i] = pk;
}

// ---------------- graph preprocessing --------------------------------------
__global__ void zero_deg_kernel() {
    int i = blockIdx.x * blockDim.x + threadIdx.x;
    if (i < N_NODES) { g_deg_out[i] = 0; g_deg_in[i] = 0; }
}

__global__ void count_deg_kernel(const int* __restrict__ src,
                                 const int* __restrict__ dst) {
    int t = blockIdx.x * blockDim.x + threadIdx.x;
    int base = t * 4;
    if (base + 3 < N_EDGES) {
        int4 s = *(const int4*)(src + base);
        int4 d = *(const int4*)(dst + base);
        atomicAdd(&g_deg_out[s.x], 1); atomicAdd(&g_deg_out[s.y], 1);
        atomicAdd(&g_deg_out[s.z], 1); atomicAdd(&g_deg_out[s.w], 1);
        atomicAdd(&g_deg_in[d.x], 1);  atomicAdd(&g_deg_in[d.y], 1);
        atomicAdd(&g_deg_in[d.z], 1);  atomicAdd(&g_deg_in[d.w], 1);
    } else {
        for (int i = base; i < N_EDGES; i++) {
            atomicAdd(&g_deg_out[src[i]], 1);
            atomicAdd(&g_deg_in[dst[i]], 1);
        }
    }
}

__global__ void scanA_kernel() {
    __shared__ int warp_sum[SCAN_BLK / 32];
    int i = blockIdx.x * SCAN_BLK + threadIdx.x;
    int v = 0;
    if (i < N_NODES) {
        int din = g_deg_in[i];
        v = din;
        g_norm_out[i] = rsqrtf((float)max(g_deg_out[i], 1));
        g_norm_in[i]  = rsqrtf((float)max(din, 1));
    }
    int s = v;
#pragma unroll
    for (int off = 16; off > 0; off >>= 1)
        s += __shfl_down_sync(0xffffffffu, s, off);
    if ((threadIdx.x & 31) == 0) warp_sum[threadIdx.x >> 5] = s;
    __syncthreads();
    if (threadIdx.x < SCAN_BLK / 32) {
        int ws = warp_sum[threadIdx.x];
#pragma unroll
        for (int off = SCAN_BLK / 64; off > 0; off >>= 1)
            ws += __shfl_down_sync(0xffffffffu, ws, off);
        if (threadIdx.x == 0) g_blocksum[blockIdx.x] = ws;
    }
}

__global__ void scanB_kernel() {
    __shared__ int sm[SCAN_NBLK];
    int t = threadIdx.x;
    int v = (t < SCAN_NBLK) ? g_blocksum[t] : 0;
    if (t < SCAN_NBLK) sm[t] = v;
    __syncthreads();
    for (int off = 1; off < SCAN_NBLK; off <<= 1) {
        int add = 0;
        if (t < SCAN_NBLK && t >= off) add = sm[t - off];
        __syncthreads();
        if (t < SCAN_NBLK && t >= off) sm[t] += add;
        __syncthreads();
    }
    if (t < SCAN_NBLK) g_blockoff[t] = sm[t] - v;
    if (t == 0) g_rowptr[N_NODES] = N_EDGES;
}

__global__ void scanC_kernel() {
    __shared__ int sm[SCAN_BLK];
    int i = blockIdx.x * SCAN_BLK + threadIdx.x;
    int t = threadIdx.x;
    int v = (i < N_NODES) ? g_deg_in[i] : 0;
    sm[t] = v;
    __syncthreads();
#pragma unroll
    for (int off = 1; off < SCAN_BLK; off <<= 1) {
        int add = (t >= off) ? sm[t - off] : 0;
        __syncthreads();
        sm[t] += add;
        __syncthreads();
    }
    if (i < N_NODES) {
        int rp = g_blockoff[blockIdx.x] + sm[t] - v;
        g_rowptr[i] = rp;
        g_cursor[i] = rp;
    }
}

__global__ void bucket_kernel(const int* __restrict__ src,
                              const int* __restrict__ dst) {
    int i = blockIdx.x * blockDim.x + threadIdx.x;
    if (i < N_EDGES) {
        int d = dst[i];
        int pos = atomicAdd(&g_cursor[d], 1);
        g_csr_src[pos] = src[i];
    }
}

__global__ void sort_csr_kernel() {
    int n = blockIdx.x * blockDim.x + threadIdx.x;
    if (n >= N_NODES) return;
    int beg = g_rowptr[n], end = g_rowptr[n + 1];
    int d = end - beg;
    if (d <= 1) return;
    if (d <= MAXDEG_LOCAL) {
        int buf[MAXDEG_LOCAL];
        for (int i = 0; i < d; i++) buf[i] = g_csr_src[beg + i];
        for (int i = 1; i < d; i++) {
            int v = buf[i];
            int j = i - 1;
            while (j >= 0 && buf[j] > v) { buf[j + 1] = buf[j]; j--; }
            buf[j + 1] = v;
        }
        for (int i = 0; i < d; i++) g_csr_src[beg + i] = buf[i];
    } else {
        for (int i = beg + 1; i < end; i++) {
            int v = g_csr_src[i];
            int j = i - 1;
            while (j >= beg && g_csr_src[j] > v) {
                g_csr_src[j + 1] = g_csr_src[j];
                j--;
            }
            g_csr_src[j + 1] = v;
        }
    }
}

// ---------------- SpMM (bf16 gather, norm pre-folded, fp32 accumulate) ------
__device__ __forceinline__ float bf_lo(uint32_t u) {
    return __uint_as_float(u << 16);
}
__device__ __forceinline__ float bf_hi(uint32_t u) {
    return __uint_as_float(u & 0xffff0000u);
}

__global__ void spmm_kernel(int in_sel) {
    const __nv_bfloat16* __restrict__ in =
        (in_sel == 0) ? g_fb : ((in_sel == 1) ? g_hb0 : g_hb1);
    int gwarp = (blockIdx.x * blockDim.x + threadIdx.x) >> 5;
    int lane = threadIdx.x & 31;
    if (gwarp >= N_NODES) return;
    int beg = g_rowptr[gwarp], end = g_rowptr[gwarp + 1];
    int off = lane * 4;
    float4 acc = make_float4(0.f, 0.f, 0.f, 0.f);
    int e = beg;
    for (; e + 3 < end; e += 4) {
        int s0 = g_csr_src[e],     s1 = g_csr_src[e + 1];
        int s2 = g_csr_src[e + 2], s3 = g_csr_src[e + 3];
        uint2 r0 = *(const uint2*)(in + s0 * D + off);
        uint2 r1 = *(const uint2*)(in + s1 * D + off);
        uint2 r2 = *(const uint2*)(in + s2 * D + off);
        uint2 r3 = *(const uint2*)(in + s3 * D + off);
        acc.x += bf_lo(r0.x) + bf_lo(r1.x) + bf_lo(r2.x) + bf_lo(r3.x);
        acc.y += bf_hi(r0.x) + bf_hi(r1.x) + bf_hi(r2.x) + bf_hi(r3.x);
        acc.z += bf_lo(r0.y) + bf_lo(r1.y) + bf_lo(r2.y) + bf_lo(r3.y);
        acc.w += bf_hi(r0.y) + bf_hi(r1.y) + bf_hi(r2.y) + bf_hi(r3.y);
    }
    for (; e < end; e++) {
        int s0 = g_csr_src[e];
        uint2 r0 = *(const uint2*)(in + s0 * D + off);
        acc.x += bf_lo(r0.x); acc.y += bf_hi(r0.x);
        acc.z += bf_lo(r0.y); acc.w += bf_hi(r0.y);
    }
    float ni = g_norm_in[gwarp];
    acc.x *= ni; acc.y *= ni; acc.z *= ni; acc.w *= ni;
    ((float4*)(g_agg + (size_t)gwarp * D))[lane] = acc;
}

// ---------------- GEMM via mma.sync bf16, 2 passes + bias + relu ------------
// block = 128 thr (4 warps), tile 64 rows x 128 cols, K=128 (R14-proven).
// out_sel 0/1: store relu(.)*norm_out as bf16 to g_hb0/g_hb1 (feeds SpMM).
// out_sel 2:   store relu(.) as fp32 to g_h0 (feeds pooling).
#define AS_STRB 272                         // 136 bf16 per row (pad)
#define SM_A    0
#define SM_BHI  (SM_A + 64 * AS_STRB)       // 17408
#define SM_BLO  (SM_BHI + 128 * AS_STRB)    // 52224
#define SM_TOT  (SM_BLO + 128 * AS_STRB)    // 87040

__device__ __forceinline__ void mma_bf16(float* c, const uint32_t* a,
                                         uint32_t b0, uint32_t b1) {
    asm volatile(
        "mma.sync.aligned.m16n8k16.row.col.f32.bf16.bf16.f32 "
        "{%0,%1,%2,%3}, {%4,%5,%6,%7}, {%8,%9}, {%0,%1,%2,%3};"
        : "+f"(c[0]), "+f"(c[1]), "+f"(c[2]), "+f"(c[3])
        : "r"(a[0]), "r"(a[1]), "r"(a[2]), "r"(a[3]), "r"(b0), "r"(b1));
}

__global__ void __launch_bounds__(128, 2)
gemm_mma_kernel(const __nv_bfloat16* __restrict__ Wthi,
                const __nv_bfloat16* __restrict__ Wtlo,
                const float* __restrict__ bl, int out_sel) {
    extern __shared__ char smem[];
    const int tid = threadIdx.x;
    const int wid = tid >> 5, lane = tid & 31;
    const int row0 = blockIdx.x * 64;

    // --- stage A tile (fp32 agg -> single bf16): thread -> row t/2, half t&1
    {
        int r = tid >> 1, ch = tid & 1;
        int grow = row0 + r;
        bool valid = grow < N_NODES;
        const float4* __restrict__ arow =
            (const float4*)(g_agg + (size_t)(valid ? grow : 0) * D);
#pragma unroll
        for (int j0 = 0; j0 < 64; j0 += 8) {
            int c = ch * 64 + j0;
            float4 f0 = valid ? arow[c / 4]     : make_float4(0.f, 0.f, 0.f, 0.f);
            float4 f1 = valid ? arow[c / 4 + 1] : make_float4(0.f, 0.f, 0.f, 0.f);
            __nv_bfloat16 hi[8];
            hi[0] = __float2bfloat16(f0.x); hi[1] = __float2bfloat16(f0.y);
            hi[2] = __float2bfloat16(f0.z); hi[3] = __float2bfloat16(f0.w);
            hi[4] = __float2bfloat16(f1.x); hi[5] = __float2bfloat16(f1.y);
            hi[6] = __float2bfloat16(f1.z); hi[7] = __float2bfloat16(f1.w);
            *(uint4*)(smem + SM_A + r * AS_STRB + c * 2) = *(uint4*)hi;
        }
    }

    // --- stage B from preconverted W^T hi/lo: flat coalesced copy -----------
    {
        const uint4* __restrict__ wh = (const uint4*)Wthi;
        const uint4* __restrict__ wl = (const uint4*)Wtlo;
#pragma unroll
        for (int idx = tid; idx < 128 * 16; idx += 128) {
            int n = idx >> 4, kq = idx & 15;
            *(uint4*)(smem + SM_BHI + n * AS_STRB + kq * 16) = wh[idx];
            *(uint4*)(smem + SM_BLO + n * AS_STRB + kq * 16) = wl[idx];
        }
    }
    __syncthreads();

    // --- main loop ----------------------------------------------------------
    const int wm = wid & 1;        // row half -> +32 rows
    const int wn = wid >> 1;       // col half -> +64 cols
    const int r4 = lane >> 2;      // 0..7
    const int q  = lane & 3;       // 0..3

    float acc[2][8][4];
#pragma unroll
    for (int mt = 0; mt < 2; mt++)
#pragma unroll
        for (int nt = 0; nt < 8; nt++)
#pragma unroll
            for (int j = 0; j < 4; j++) acc[mt][nt][j] = 0.f;

    const char* As    = smem + SM_A;
    const char* Bs_hi = smem + SM_BHI;
    const char* Bs_lo = smem + SM_BLO;

#pragma unroll 2
    for (int kc = 0; kc < 8; kc++) {
        int k0 = kc * 16;
        uint32_t ah[2][4];
#pragma unroll
        for (int mt = 0; mt < 2; mt++) {
            int rm = wm * 32 + mt * 16 + r4;
            int ka = k0 + 2 * q;
            ah[mt][0] = *(const uint32_t*)(As + rm * AS_STRB + ka * 2);
            ah[mt][1] = *(const uint32_t*)(As + (rm + 8) * AS_STRB + ka * 2);
            ah[mt][2] = *(const uint32_t*)(As + rm * AS_STRB + (ka + 8) * 2);
            ah[mt][3] = *(const uint32_t*)(As + (rm + 8) * AS_STRB + (ka + 8) * 2);
        }
#pragma unroll
        for (int nt = 0; nt < 8; nt++) {
            int nn = wn * 64 + nt * 8 + r4;
            int kb = k0 + 2 * q;
            uint32_t bh0 = *(const uint32_t*)(Bs_hi + nn * AS_STRB + kb * 2);
            uint32_t bh1 = *(const uint32_t*)(Bs_hi + nn * AS_STRB + (kb + 8) * 2);
            uint32_t bl0 = *(const uint32_t*)(Bs_lo + nn * AS_STRB + kb * 2);
            uint32_t bl1 = *(const uint32_t*)(Bs_lo + nn * AS_STRB + (kb + 8) * 2);
#pragma unroll
            for (int mt = 0; mt < 2; mt++) {
                mma_bf16(acc[mt][nt], ah[mt], bh0, bh1);
                mma_bf16(acc[mt][nt], ah[mt], bl0, bl1);
            }
        }
    }

    // --- epilogue -----------------------------------------------------------
    if (out_sel < 2) {
        __nv_bfloat16* __restrict__ outb = (out_sel == 0) ? g_hb0 : g_hb1;
#pragma unroll
        for (int mt = 0; mt < 2; mt++) {
#pragma unroll
            for (int nt = 0; nt < 8; nt++) {
                int row = row0 + wm * 32 + mt * 16 + r4;
                int col = wn * 64 + nt * 8 + 2 * q;
                float2 bb = *(const float2*)(bl + col);
                if (row < N_NODES) {
                    float nw = g_norm_out[row];
                    __nv_bfloat162 v = __floats2bfloat162_rn(
                        fmaxf(acc[mt][nt][0] + bb.x, 0.f) * nw,
                        fmaxf(acc[mt][nt][1] + bb.y, 0.f) * nw);
                    *(uint32_t*)(outb + (size_t)row * D + col) = *(uint32_t*)&v;
                }
                if (row + 8 < N_NODES) {
                    float nw = g_norm_out[row + 8];
                    __nv_bfloat162 v = __floats2bfloat162_rn(
                        fmaxf(acc[mt][nt][2] + bb.x, 0.f) * nw,
                        fmaxf(acc[mt][nt][3] + bb.y, 0.f) * nw);
                    *(uint32_t*)(outb + (size_t)(row + 8) * D + col) =
                        *(uint32_t*)&v;
                }
            }
        }
    } else {
#pragma unroll
        for (int mt = 0; mt < 2; mt++) {
#pragma unroll
            for (int nt = 0; nt < 8; nt++) {
                int row = row0 + wm * 32 + mt * 16 + r4;
                int col = wn * 64 + nt * 8 + 2 * q;
                float2 bb = *(const float2*)(bl + col);
                if (row < N_NODES) {
                    float2 v;
                    v.x = fmaxf(acc[mt][nt][0] + bb.x, 0.f);
                    v.y = fmaxf(acc[mt][nt][1] + bb.y, 0.f);
                    *(float2*)(g_h0 + (size_t)row * D + col) = v;
                }
                if (row + 8 < N_NODES) {
                    float2 v;
                    v.x = fmaxf(acc[mt][nt][2] + bb.x, 0.f);
                    v.y = fmaxf(acc[mt][nt][3] + bb.y, 0.f);
                    *(float2*)(g_h0 + (size_t)(row + 8) * D + col) = v;
                }
            }
        }
    }
}

// ---------------- pooling ---------------------------------------------------
__device__ __forceinline__ int lower_bound_dev(const int* __restrict__ a,
                                               int n, int key) {
    int lo = 0, hi = n;
    while (lo < hi) {
        int mid = (lo + hi) >> 1;
        if (a[mid] < key) lo = mid + 1; else hi = mid;
    }
    return lo;
}

__global__ void pool_kernel(const int* __restrict__ gid,
                            float* __restrict__ out) {
    __shared__ int s_beg, s_end;
    int g = blockIdx.x;
    if (threadIdx.x == 0) {
        s_beg = lower_bound_dev(gid, N_NODES, g);
        s_end = lower_bound_dev(gid, N_NODES, g + 1);
    }
    __syncthreads();
    int beg = s_beg, end = s_end;
    const float* __restrict__ h = g_h0;
    float acc = 0.f;
    for (int n = beg; n < end; n++) acc += h[n * D + threadIdx.x];
    float cnt = (float)max(end - beg, 1);
    out[g * D + threadIdx.x] = acc / cnt;
}

// ---------------- launch ----------------------------------------------------
extern "C" void kernel_launch(void* const* d_in, const int* in_sizes, int n_in,
                              void* d_out, int out_size) {
    const float* feats = (const float*)d_in[0];
    const float* W     = (const float*)d_in[1];
    const float* b     = (const float*)d_in[2];
    const int*   src   = (const int*)d_in[3];
    const int*   dst   = (const int*)d_in[4];
    const int*   gid   = (const int*)d_in[5];
    float* out = (float*)d_out;

    cudaFuncSetAttribute(gemm_mma_kernel,
                         cudaFuncAttributeMaxDynamicSharedMemorySize, SM_TOT);

    __nv_bfloat16 *wthi_p, *wtlo_p;
    cudaGetSymbolAddress((void**)&wthi_p, g_Wthi);
    cudaGetSymbolAddress((void**)&wtlo_p, g_Wtlo);

    const int NODE_BLKS = (N_NODES + 255) / 256;           // 196
    const int EDGE_BLKS = (N_EDGES + 255) / 256;           // 3125
    const int CNT_BLKS  = (N_EDGES / 4 + 255) / 256;       // 782
    const int CW_BLKS   = (N_LAYERS * D * D + 255) / 256;  // 192
    const int CF_BLKS   = (N_NODES * D / 4 + 255) / 256;   // 6250

    convW_kernel<<<CW_BLKS, 256>>>(W);
    zero_deg_kernel<<<NODE_BLKS, 256>>>();
    count_deg_kernel<<<CNT_BLKS, 256>>>(src, dst);
    scanA_kernel<<<SCAN_NBLK, SCAN_BLK>>>();
    convF_kernel<<<CF_BLKS, 256>>>(feats);     // needs norm_out (after scanA)
    scanB_kernel<<<1, 256>>>();
    scanC_kernel<<<SCAN_NBLK, SCAN_BLK>>>();
    bucket_kernel<<<EDGE_BLKS, 256>>>(src, dst);
    sort_csr_kernel<<<NODE_BLKS, 256>>>();

    const int SPMM_BLKS = N_NODES / 8;                     // 6250
    const int GEMM_BLKS = (N_NODES + 63) / 64;             // 782

    spmm_kernel<<<SPMM_BLKS, 256>>>(0);
    gemm_mma_kernel<<<GEMM_BLKS, 128, SM_TOT>>>(wthi_p, wtlo_p, b + 0 * D, 0);
    spmm_kernel<<<SPMM_BLKS, 256>>>(1);
    gemm_mma_kernel<<<GEMM_BLKS, 128, SM_TOT>>>(wthi_p + D * D,
                                                wtlo_p + D * D, b + 1 * D, 1);
    spmm_kernel<<<SPMM_BLKS, 256>>>(2);
    gemm_mma_kernel<<<GEMM_BLKS, 128, SM_TOT>>>(wthi_p + 2 * D * D,
                                                wtlo_p + 2 * D * D, b + 2 * D, 2);

    pool_kernel<<<N_GRAPHS, 128>>>(gid, out);
}